// round 17
// baseline (speedup 1.0000x reference)
#include <cuda_runtime.h>
#include <cuda_bf16.h>
#include <cuda_fp16.h>
#include <math.h>
#include <stdint.h>

#define B_    4
#define N_    4096
#define DIN_  512
#define DOUT_ 128
#define MAXDEG 128
#define NEG_BIG -1e30f

// ---------------- scratch (static device memory; no allocs) ----------------
__device__ __half g_whh[B_ * N_ * DOUT_];   // x @ W (fp16)   4 MB
__device__ __half g_outh[B_ * N_ * DOUT_];  // att @ wh       4 MB
__device__ float g_sT[N_ * 4];              // s transposed [i][b]
__device__ float g_dT[N_ * 4];              // d transposed [i][b]
__device__ float g_csPart[256 * DOUT_];     // per-CTA colsum partials
__device__ int   g_cols[N_ * MAXDEG];
__device__ int   g_deg[N_];

// ============================ helpers =======================================
__device__ __forceinline__ uint32_t smem_u32(const void* p) {
    uint32_t a;
    asm("{ .reg .u64 t; cvta.to.shared.u64 t, %1; cvt.u32.u64 %0, t; }" : "=r"(a) : "l"(p));
    return a;
}
__device__ __forceinline__ void ldm_x4(uint32_t* f, uint32_t addr) {
    asm volatile("ldmatrix.sync.aligned.m8n8.x4.shared.b16 {%0,%1,%2,%3}, [%4];"
                 : "=r"(f[0]), "=r"(f[1]), "=r"(f[2]), "=r"(f[3]) : "r"(addr));
}
__device__ __forceinline__ void ldm_x4t(uint32_t* f, uint32_t addr) {
    asm volatile("ldmatrix.sync.aligned.m8n8.x4.trans.shared.b16 {%0,%1,%2,%3}, [%4];"
                 : "=r"(f[0]), "=r"(f[1]), "=r"(f[2]), "=r"(f[3]) : "r"(addr));
}
__device__ __forceinline__ void mma_f16(float* c, const uint32_t* a, const uint32_t* b) {
    asm volatile(
        "mma.sync.aligned.m16n8k16.row.col.f32.f16.f16.f32 "
        "{%0,%1,%2,%3}, {%4,%5,%6,%7}, {%8,%9}, {%0,%1,%2,%3};"
        : "+f"(c[0]), "+f"(c[1]), "+f"(c[2]), "+f"(c[3])
        : "r"(a[0]), "r"(a[1]), "r"(a[2]), "r"(a[3]), "r"(b[0]), "r"(b[1]));
}
__device__ __forceinline__ uint32_t pack_half(float x, float y) {
    __half2 h = __floats2half2_rn(x, y);
    return *(uint32_t*)&h;
}

// =============== CSR build: warp/row, 4 loads in flight ====================
__global__ void csr_build_kernel(const float* __restrict__ adj) {
    int warp = (blockIdx.x * blockDim.x + threadIdx.x) >> 5;
    int lane = threadIdx.x & 31;
    if (warp >= N_) return;
    const float4* row = (const float4*)(adj + (size_t)warp * N_);
    int cnt = 0;
    for (int base = 0; base < N_; base += 512) {
        float4 v0 = row[(base >> 2) + lane];
        float4 v1 = row[(base >> 2) + 32 + lane];
        float4 v2 = row[(base >> 2) + 64 + lane];
        float4 v3 = row[(base >> 2) + 96 + lane];
        float c16[16] = {v0.x, v0.y, v0.z, v0.w, v1.x, v1.y, v1.z, v1.w,
                         v2.x, v2.y, v2.z, v2.w, v3.x, v3.y, v3.z, v3.w};
#pragma unroll
        for (int h = 0; h < 4; h++) {
#pragma unroll
            for (int c = 0; c < 4; c++) {
                float f = c16[h * 4 + c];
                unsigned m = __ballot_sync(0xffffffffu, f > 0.0f);
                if (f > 0.0f) {
                    int pos = cnt + __popc(m & ((1u << lane) - 1u));
                    if (pos < MAXDEG)
                        g_cols[warp * MAXDEG + pos] = base + h * 128 + lane * 4 + c;
                }
                cnt += __popc(m);
            }
        }
    }
    if (lane == 0) g_deg[warp] = cnt < MAXDEG ? cnt : MAXDEG;
}

// ===== HMMA GEMM (fp16, inline W convert): wh = x @ W ======================
#define KC 32
#define NCH (DIN_ / KC)          // 16
#define A_STG 8192               // 64 rows * 128B
#define B_STG 8192               // 32 k * 128 n * 2B
#define SM_A 0
#define SM_B (2 * A_STG)
#define SM_SD (SM_B + 2 * B_STG)          // s_sm[64], d_sm[64]
#define SM_AV (SM_SD + 512)               // a_s[128], a_d[128]
#define SM_CS (SM_AV + 1024)              // cs[128]
#define SMEM_TOTAL (SM_CS + 512)

__device__ __forceinline__ uint32_t a_off(int r, int gran) {
    return (uint32_t)(r * 128 + ((gran ^ (r & 7)) << 4));
}
__device__ __forceinline__ uint32_t b_off2(int k, int gran) {
    return (uint32_t)(k * 256 + ((gran ^ (k & 7)) << 4));
}

__global__ __launch_bounds__(256, 2) void gemm_hmma_kernel(
    const float* __restrict__ x, const float* __restrict__ W,
    const float* __restrict__ a) {
    extern __shared__ char smem[];
    const uint32_t sb = smem_u32(smem);
    const int tid = threadIdx.x;
    const int wid = tid >> 5, lane = tid & 31;
    const int wm = wid >> 1, wn = wid & 1;     // warp tile: 16 rows x 64 cols
    const int tig = lane & 3, grp = lane >> 2;

    float* s_sm = (float*)(smem + SM_SD);
    float* d_sm = (float*)(smem + SM_SD + 256);
    float* a_s  = (float*)(smem + SM_AV);
    float* a_d  = (float*)(smem + SM_AV + 512);
    float* cs   = (float*)(smem + SM_CS);
    if (tid < 128) {
        cs[tid] = 0.0f;
        a_s[tid] = a[tid]; a_d[tid] = a[DOUT_ + tid];
    }
    if (tid < 64) { s_sm[tid] = 0.0f; d_sm[tid] = 0.0f; }

    const int R0 = blockIdx.x * 64;
    const int arow = tid >> 2, akoff = (tid & 3) * 8;
    const float* pA = x + (size_t)(R0 + arow) * DIN_ + akoff;
    const int bk = tid >> 3, bgr = (tid & 7) * 2;
    const float4* W4 = (const float4*)W;
    const int wbase = bk * 32 + bgr * 2;    // float4 index within chunk

    float acc[8][4];
#pragma unroll
    for (int j = 0; j < 8; j++)
#pragma unroll
        for (int q = 0; q < 4; q++) acc[j][q] = 0.0f;

    float4 ra[2];
    float4 rbw[4];
    ra[0] = *(const float4*)(pA);
    ra[1] = *(const float4*)(pA + 4);
#pragma unroll
    for (int q = 0; q < 4; q++) rbw[q] = W4[wbase + q];

    for (int c = 0; c < NCH; c++) {
        const int buf = c & 1;
        char* Abuf = smem + SM_A + buf * A_STG;
        char* Bbuf = smem + SM_B + buf * B_STG;

        {
            const float* fa = (const float*)ra;
#pragma unroll
            for (int p = 0; p < 4; p++) {
                uint32_t hv = pack_half(fa[2 * p], fa[2 * p + 1]);
                int kl = akoff + 2 * p;
                int gr = kl >> 3, wi = (kl & 7) * 2;
                *(uint32_t*)(Abuf + a_off(arow, gr) + wi) = hv;
            }
            uint4 u0, u1;
            u0.x = pack_half(rbw[0].x, rbw[0].y); u0.y = pack_half(rbw[0].z, rbw[0].w);
            u0.z = pack_half(rbw[1].x, rbw[1].y); u0.w = pack_half(rbw[1].z, rbw[1].w);
            u1.x = pack_half(rbw[2].x, rbw[2].y); u1.y = pack_half(rbw[2].z, rbw[2].w);
            u1.z = pack_half(rbw[3].x, rbw[3].y); u1.w = pack_half(rbw[3].z, rbw[3].w);
            *(uint4*)(Bbuf + b_off2(bk, bgr))     = u0;
            *(uint4*)(Bbuf + b_off2(bk, bgr + 1)) = u1;
        }
        __syncthreads();

        if (c + 1 < NCH) {
            const float* qA = pA + (c + 1) * KC;
            ra[0] = *(const float4*)(qA);
            ra[1] = *(const float4*)(qA + 4);
            int gi = (c + 1) * 1024 + wbase;   // chunk = 32 rows * 32 f4
#pragma unroll
            for (int q = 0; q < 4; q++) rbw[q] = W4[gi + q];
        }

        const uint32_t Abase = sb + SM_A + buf * A_STG;
        const uint32_t Bbase = sb + SM_B + buf * B_STG;
#pragma unroll
        for (int ks = 0; ks < 2; ks++) {
            uint32_t ahi[4];
            {
                int R = wm * 16 + (lane & 15);
                int gh = 2 * ks + (lane >> 4);
                ldm_x4(ahi, Abase + a_off(R, gh));
            }
            int kk = 16 * ks + (lane & 15);
#pragma unroll
            for (int ntp = 0; ntp < 4; ntp++) {
                int gn = wn * 8 + ntp * 2 + (lane >> 4);
                uint32_t bb[4];
                ldm_x4t(bb, Bbase + b_off2(kk, gn));
                mma_f16(acc[ntp * 2],     ahi, bb);
                mma_f16(acc[ntp * 2 + 1], ahi, bb + 2);
            }
        }
        __syncthreads();
    }

    // ---- epilogue: store wh (fp16), fused s/d dots + column-sum partials ----
    float sacc[2] = {0, 0}, dacc[2] = {0, 0};
    int rbase = R0 + wm * 16 + grp;
#pragma unroll
    for (int nt = 0; nt < 8; nt++) {
        int col = wn * 64 + nt * 8 + tig * 2;
        float* cf = acc[nt];
        sacc[0] += cf[0] * a_s[col] + cf[1] * a_s[col + 1];
        sacc[1] += cf[2] * a_s[col] + cf[3] * a_s[col + 1];
        dacc[0] += cf[0] * a_d[col] + cf[1] * a_d[col + 1];
        dacc[1] += cf[2] * a_d[col] + cf[3] * a_d[col + 1];
        *(__half2*)&g_whh[(size_t)rbase * DOUT_ + col] =
            __float22half2_rn(make_float2(cf[0], cf[1]));
        *(__half2*)&g_whh[(size_t)(rbase + 8) * DOUT_ + col] =
            __float22half2_rn(make_float2(cf[2], cf[3]));

        float v0 = cf[0] + cf[2];
        float v1 = cf[1] + cf[3];
#pragma unroll
        for (int off = 16; off >= 4; off >>= 1) {
            v0 += __shfl_down_sync(0xffffffffu, v0, off);
            v1 += __shfl_down_sync(0xffffffffu, v1, off);
        }
        if (lane < 4) {
            atomicAdd(&cs[col], v0);
            atomicAdd(&cs[col + 1], v1);
        }
    }
#pragma unroll
    for (int h = 0; h < 2; h++) {
        sacc[h] += __shfl_xor_sync(0xffffffffu, sacc[h], 1);
        sacc[h] += __shfl_xor_sync(0xffffffffu, sacc[h], 2);
        dacc[h] += __shfl_xor_sync(0xffffffffu, dacc[h], 1);
        dacc[h] += __shfl_xor_sync(0xffffffffu, dacc[h], 2);
    }
    if (tig == 0) {
        int r = wm * 16 + grp;
        atomicAdd(&s_sm[r], sacc[0]);
        atomicAdd(&s_sm[r + 8], sacc[1]);
        atomicAdd(&d_sm[r], dacc[0]);
        atomicAdd(&d_sm[r + 8], dacc[1]);
    }
    __syncthreads();
    if (tid < 64) {
        int b = R0 / N_;
        int il = (R0 % N_) + tid;
        g_sT[il * 4 + b] = s_sm[tid];
        g_dT[il * 4 + b] = d_sm[tid];
    }
    if (tid < 128) g_csPart[blockIdx.x * DOUT_ + tid] = cs[tid];
}

// ==== attention SpMM: warp per (row, graph-pair); persistent single wave ====
#define AF_GRID 512
#define NUNITS (N_ / 4)   // 1024

__global__ __launch_bounds__(256) void attn_kernel() {
    __shared__ float sh_e[8][MAXDEG][2];
    __shared__ int   sh_j[8][MAXDEG];
    int lane = threadIdx.x & 31;
    int w = threadIdx.x >> 5;
    int rl = w >> 1, pr = w & 1;
    int b0 = 2 * pr;

    for (int u = blockIdx.x; u < NUNITS; u += AF_GRID) {
        int i = u * 4 + rl;
        int deg = g_deg[i];

        if (deg == 0) {
            float inv = 1.0f / (float)N_;
#pragma unroll
            for (int q = 0; q < 2; q++) {
                int b = b0 + q;
                float4 m0 = make_float4(0, 0, 0, 0);
                for (int c = 0; c < 64; c++) {
                    float4 p = ((const float4*)&g_csPart[(b * 64 + c) * DOUT_])[lane];
                    m0.x += p.x; m0.y += p.y; m0.z += p.z; m0.w += p.w;
                }
                uint2 o;
                o.x = pack_half(m0.x * inv, m0.y * inv);
                o.y = pack_half(m0.z * inv, m0.w * inv);
                ((uint2*)&g_outh[((size_t)b * N_ + i) * DOUT_])[lane] = o;
            }
            continue;
        }

        float2 s2 = *(const float2*)&g_sT[i * 4 + b0];
        float mx0 = NEG_BIG, mx1 = NEG_BIG;
        for (int t = lane; t < deg; t += 32) {
            int j = g_cols[i * MAXDEG + t];
            sh_j[w][t] = j;
            float2 d2 = *(const float2*)&g_dT[j * 4 + b0];
            float e0 = s2.x + d2.x; e0 = e0 > 0.f ? e0 : 0.01f * e0;
            float e1 = s2.y + d2.y; e1 = e1 > 0.f ? e1 : 0.01f * e1;
            *(float2*)sh_e[w][t] = make_float2(e0, e1);
            mx0 = fmaxf(mx0, e0); mx1 = fmaxf(mx1, e1);
        }
#pragma unroll
        for (int off = 16; off > 0; off >>= 1) {
            mx0 = fmaxf(mx0, __shfl_xor_sync(0xffffffffu, mx0, off));
            mx1 = fmaxf(mx1, __shfl_xor_sync(0xffffffffu, mx1, off));
        }
        __syncwarp();

        float se0 = 0.f, se1 = 0.f;
        for (int t = lane; t < deg; t += 32) {
            float2 e = *(float2*)sh_e[w][t];
            float p0 = __expf(e.x - mx0), p1 = __expf(e.y - mx1);
            *(float2*)sh_e[w][t] = make_float2(p0, p1);
            se0 += p0; se1 += p1;
        }
#pragma unroll
        for (int off = 16; off > 0; off >>= 1) {
            se0 += __shfl_xor_sync(0xffffffffu, se0, off);
            se1 += __shfl_xor_sync(0xffffffffu, se1, off);
        }
        float iv0 = 1.f / se0, iv1 = 1.f / se1;
        __syncwarp();

        const uint2* whA = (const uint2*)g_whh + (size_t)b0 * N_ * 32;
        const uint2* whB = whA + (size_t)N_ * 32;
        float aA0 = 0.f, aA1 = 0.f, aA2 = 0.f, aA3 = 0.f;
        float aB0 = 0.f, aB1 = 0.f, aB2 = 0.f, aB3 = 0.f;

        int k = 0;
        for (; k + 4 <= deg; k += 4) {
            uint2 vA[4], vB[4];
            float pA[4], pB[4];
#pragma unroll
            for (int uu = 0; uu < 4; uu++) {
                size_t o = (size_t)sh_j[w][k + uu] * 32 + lane;
                vA[uu] = whA[o]; vB[uu] = whB[o];
                float2 p = *(float2*)sh_e[w][k + uu];
                pA[uu] = p.x * iv0; pB[uu] = p.y * iv1;
            }
#pragma unroll
            for (int uu = 0; uu < 4; uu++) {
                float2 f;
                f = __half22float2(*(__half2*)&vA[uu].x); aA0 += pA[uu] * f.x; aA1 += pA[uu] * f.y;
                f = __half22float2(*(__half2*)&vA[uu].y); aA2 += pA[uu] * f.x; aA3 += pA[uu] * f.y;
                f = __half22float2(*(__half2*)&vB[uu].x); aB0 += pB[uu] * f.x; aB1 += pB[uu] * f.y;
                f = __half22float2(*(__half2*)&vB[uu].y); aB2 += pB[uu] * f.x; aB3 += pB[uu] * f.y;
            }
        }
        for (; k < deg; k++) {
            size_t o0 = (size_t)sh_j[w][k] * 32 + lane;
            uint2 vA0 = whA[o0], vB0 = whB[o0];
            float2 p0 = *(float2*)sh_e[w][k];
            float pA0 = p0.x * iv0, pB0 = p0.y * iv1;
            float2 f;
            f = __half22float2(*(__half2*)&vA0.x); aA0 += pA0 * f.x; aA1 += pA0 * f.y;
            f = __half22float2(*(__half2*)&vA0.y); aA2 += pA0 * f.x; aA3 += pA0 * f.y;
            f = __half22float2(*(__half2*)&vB0.x); aB0 += pB0 * f.x; aB1 += pB0 * f.y;
            f = __half22float2(*(__half2*)&vB0.y); aB2 += pB0 * f.x; aB3 += pB0 * f.y;
        }
        uint2 oA, oB;
        oA.x = pack_half(aA0, aA1); oA.y = pack_half(aA2, aA3);
        oB.x = pack_half(aB0, aB1); oB.y = pack_half(aB2, aB3);
        ((uint2*)&g_outh[((size_t)b0 * N_ + i) * DOUT_])[lane] = oA;
        ((uint2*)&g_outh[((size_t)(b0 + 1) * N_ + i) * DOUT_])[lane] = oB;
    }
}

// ==== final: y = relu(adj @ out); persistent single wave ====================
__global__ __launch_bounds__(256) void final_kernel(float* __restrict__ y) {
    int lane = threadIdx.x & 31;
    int w = threadIdx.x >> 5;
    int rl = w >> 1, pr = w & 1;
    int b0 = 2 * pr;

    for (int u = blockIdx.x; u < NUNITS; u += AF_GRID) {
        int i = u * 4 + rl;
        int deg = g_deg[i];

        const uint2* ouA = (const uint2*)g_outh + (size_t)b0 * N_ * 32;
        const uint2* ouB = ouA + (size_t)N_ * 32;
        float aA0 = 0.f, aA1 = 0.f, aA2 = 0.f, aA3 = 0.f;
        float aB0 = 0.f, aB1 = 0.f, aB2 = 0.f, aB3 = 0.f;

        int k = 0;
        for (; k + 4 <= deg; k += 4) {
            uint2 vA[4], vB[4];
#pragma unroll
            for (int uu = 0; uu < 4; uu++) {
                size_t o = (size_t)g_cols[i * MAXDEG + k + uu] * 32 + lane;
                vA[uu] = ouA[o]; vB[uu] = ouB[o];
            }
#pragma unroll
            for (int uu = 0; uu < 4; uu++) {
                float2 f;
                f = __half22float2(*(__half2*)&vA[uu].x); aA0 += f.x; aA1 += f.y;
                f = __half22float2(*(__half2*)&vA[uu].y); aA2 += f.x; aA3 += f.y;
                f = __half22float2(*(__half2*)&vB[uu].x); aB0 += f.x; aB1 += f.y;
                f = __half22float2(*(__half2*)&vB[uu].y); aB2 += f.x; aB3 += f.y;
            }
        }
        for (; k < deg; k++) {
            size_t o0 = (size_t)g_cols[i * MAXDEG + k] * 32 + lane;
            uint2 vA0 = ouA[o0], vB0 = ouB[o0];
            float2 f;
            f = __half22float2(*(__half2*)&vA0.x); aA0 += f.x; aA1 += f.y;
            f = __half22float2(*(__half2*)&vA0.y); aA2 += f.x; aA3 += f.y;
            f = __half22float2(*(__half2*)&vB0.x); aB0 += f.x; aB1 += f.y;
            f = __half22float2(*(__half2*)&vB0.y); aB2 += f.x; aB3 += f.y;
        }
        float4 rA = make_float4(fmaxf(aA0, 0.f), fmaxf(aA1, 0.f),
                                fmaxf(aA2, 0.f), fmaxf(aA3, 0.f));
        float4 rB = make_float4(fmaxf(aB0, 0.f), fmaxf(aB1, 0.f),
                                fmaxf(aB2, 0.f), fmaxf(aB3, 0.f));
        ((float4*)&y[((size_t)b0 * N_ + i) * DOUT_])[lane] = rA;
        ((float4*)&y[((size_t)(b0 + 1) * N_ + i) * DOUT_])[lane] = rB;
    }
}

// ---------------- launch ----------------
extern "C" void kernel_launch(void* const* d_in, const int* in_sizes, int n_in,
                              void* d_out, int out_size) {
    const float* x   = (const float*)d_in[0];  // (B, N, DIN)
    const float* adj = (const float*)d_in[1];  // (N, N)
    const float* wts = (const float*)d_in[2];  // (DIN, DOUT)
    const float* a   = (const float*)d_in[3];  // (2*DOUT, 1)
    float* y = (float*)d_out;

    static cudaStream_t s2;
    static cudaEvent_t evA, evC;
    static int inited = 0;
    if (!inited) {
        cudaFuncSetAttribute(gemm_hmma_kernel,
                             cudaFuncAttributeMaxDynamicSharedMemorySize, SMEM_TOTAL);
        cudaStreamCreateWithFlags(&s2, cudaStreamNonBlocking);
        cudaEventCreateWithFlags(&evA, cudaEventDisableTiming);
        cudaEventCreateWithFlags(&evC, cudaEventDisableTiming);
        inited = 1;
    }
    cudaStream_t s0 = 0;

    // fork: csr on s2 overlaps GEMM on s0; join before attn
    cudaEventRecord(evA, s0);
    cudaStreamWaitEvent(s2, evA, 0);
    csr_build_kernel<<<N_ / 8, 256, 0, s2>>>(adj);
    cudaEventRecord(evC, s2);

    gemm_hmma_kernel<<<(B_ * N_) / 64, 256, SMEM_TOTAL, s0>>>(x, wts, a);
    cudaStreamWaitEvent(s0, evC, 0);

    attn_kernel<<<AF_GRID, 256, 0, s0>>>();
    final_kernel<<<AF_GRID, 256, 0, s0>>>(y);
}